// round 3
// baseline (speedup 1.0000x reference)
#include <cuda_runtime.h>
#include <math.h>

// Problem constants (fixed by reference: x = (4, 64, 128, 128) fp32)
#define HH 128
#define WW 128
#define BB 4

// Scratch (allocation-free: __device__ globals)
__device__ float g_A[BB * 128 * HH * WW];   // 32 MB ping
__device__ float g_B[BB * 128 * HH * WW];   // 32 MB pong
__device__ float g_off[BB * 18 * HH * WW];  // offsets
__device__ float g_wtc[128 * 9 * 128];      // transposed conv weights  [cin*9][OP]
__device__ float g_wto[128 * 9 * 24];       // transposed offset-conv weights (pad 24)
__device__ float g_wtd[128 * 9 * 128];      // transposed deform weights [c*9+k][O]

__device__ __forceinline__ float lrelu(float v) { return v >= 0.f ? v : 0.2f * v; }

// ---------------------------------------------------------------------------
// Weight transpose + pad: wt[j*OP + o] = (o < O) ? w[o*C9 + j] : 0
// ---------------------------------------------------------------------------
__global__ void wt_pad_kernel(const float* __restrict__ w, float* __restrict__ wt,
                              int C9, int O, int OP)
{
    int idx = blockIdx.x * 256 + threadIdx.x;
    if (idx < C9 * OP) {
        int j = idx / OP;
        int o = idx - j * OP;
        wt[idx] = (o < O) ? w[o * C9 + j] : 0.f;
    }
}

// ---------------------------------------------------------------------------
// Plain 3x3 conv, stride 1, pad 1, optional LeakyReLU.
// Tile: 32(x) x 16(y) pixels, OCB output channels per block, 128 threads.
// Thread = (lx 0..7, ly 0..15): 4 px x OCB oc accumulators.
// Weights staged per-4-cin-chunk from pre-transposed [cin*9][OP].
// ---------------------------------------------------------------------------
template<int CIN, int OCB, bool RELU>
__global__ __launch_bounds__(128)
void conv3x3_kernel(const float* __restrict__ x, const float* __restrict__ wt,
                    const float* __restrict__ bias, float* __restrict__ y,
                    int Cout, int OP, int n_ocb)
{
    __shared__ float w_s[36][OCB];
    __shared__ float in_s[4][18][34];

    const int t   = threadIdx.x;
    const int lx  = t & 7;
    const int ly  = t >> 3;
    const int bx  = blockIdx.x * 32;
    const int by  = blockIdx.y * 16;
    const int b   = blockIdx.z / n_ocb;
    const int ocb = blockIdx.z % n_ocb;
    const int oc0 = ocb * OCB;

    float bv[OCB];
    #pragma unroll
    for (int i = 0; i < OCB; i++)
        bv[i] = (oc0 + i < Cout) ? bias[oc0 + i] : 0.f;

    float acc[OCB][4];
    #pragma unroll
    for (int i = 0; i < OCB; i++)
        #pragma unroll
        for (int p = 0; p < 4; p++) acc[i][p] = 0.f;

    const float* xb = x + b * CIN * HH * WW;

    for (int c0 = 0; c0 < CIN; c0 += 4) {
        __syncthreads();
        // Stage this chunk's weights: rows [c0*9, c0*9+36), cols [oc0, oc0+OCB)
        for (int i = t; i < 36 * OCB; i += 128) {
            int row = i / OCB;
            int col = i - row * OCB;
            w_s[row][col] = wt[(c0 * 9 + row) * OP + oc0 + col];
        }
        // Load 4 input channels of a (16+2) x (32+2) halo tile
        for (int i = t; i < 4 * 18 * 34; i += 128) {
            int cc  = i / (18 * 34);
            int rem = i - cc * (18 * 34);
            int r   = rem / 34;
            int col = rem - r * 34;
            int gy  = by - 1 + r;
            int gx  = bx - 1 + col;
            float v = 0.f;
            if ((unsigned)gy < (unsigned)HH && (unsigned)gx < (unsigned)WW)
                v = xb[(c0 + cc) * HH * WW + gy * WW + gx];
            in_s[cc][r][col] = v;
        }
        __syncthreads();
        #pragma unroll
        for (int cc = 0; cc < 4; cc++) {
            float in[3][6];
            #pragma unroll
            for (int r = 0; r < 3; r++)
                #pragma unroll
                for (int cl = 0; cl < 6; cl++)
                    in[r][cl] = in_s[cc][ly + r][lx * 4 + cl];
            #pragma unroll
            for (int j = 0; j < 9; j++) {
                int ry = j / 3, rx = j - ry * 3;
                #pragma unroll
                for (int q = 0; q < OCB / 4; q++) {
                    float4 w4 = *(float4*)&w_s[cc * 9 + j][q * 4];
                    #pragma unroll
                    for (int p = 0; p < 4; p++) {
                        float iv = in[ry][p + rx];
                        acc[q * 4 + 0][p] += iv * w4.x;
                        acc[q * 4 + 1][p] += iv * w4.y;
                        acc[q * 4 + 2][p] += iv * w4.z;
                        acc[q * 4 + 3][p] += iv * w4.w;
                    }
                }
            }
        }
    }

    const int gy = by + ly;
    const int gx = bx + lx * 4;
    #pragma unroll
    for (int oc = 0; oc < OCB; oc++) {
        if (oc0 + oc < Cout) {
            float v0 = acc[oc][0] + bv[oc];
            float v1 = acc[oc][1] + bv[oc];
            float v2 = acc[oc][2] + bv[oc];
            float v3 = acc[oc][3] + bv[oc];
            if (RELU) { v0 = lrelu(v0); v1 = lrelu(v1); v2 = lrelu(v2); v3 = lrelu(v3); }
            float4 r4 = make_float4(v0, v1, v2, v3);
            *(float4*)&y[((b * Cout + oc0 + oc) * HH + gy) * WW + gx] = r4;
        }
    }
}

// ---------------------------------------------------------------------------
// Deformable 3x3 conv + LeakyReLU (torchvision semantics, no modulation).
// Block: 128 threads, 64 consecutive x pixels on one row, all O channels.
// CC=4 channel chunk. Thread = (og 0..15, pg 0..7): OT oc x 8 px accums
// (64 accs for O=128). Phase B: per k-step 4x LDS.128 -> 8*OT FFMA.
// smem ~36.9KB (O=128) -> ~5 CTAs/SM.
// ---------------------------------------------------------------------------
template<int C, int O>
__global__ __launch_bounds__(128)
void dconv3x3_kernel(const float* __restrict__ x, const float* __restrict__ off,
                     const float* __restrict__ wt, const float* __restrict__ bias,
                     float* __restrict__ y)
{
    constexpr int CC = 4;
    constexpr int PX = 64;
    constexpr int OT = O / 16;          // 8 (O=128) or 4 (O=64)
    extern __shared__ float dsm[];
    float* t_wy  = dsm;                      // 576
    float* t_wx  = dsm + 576;                // 576
    int*   t_y0  = (int*)(dsm + 1152);       // 576
    int*   t_x0  = (int*)(dsm + 1728);       // 576
    float* val_s = dsm + 2304;               // CC*9*PX = 2304
    float* w_s   = dsm + 2304 + CC * 9 * PX; // CC*9*O

    const int t  = threadIdx.x;
    const int og = t >> 3;               // 0..15
    const int pg = t & 7;                // 0..7  (px base = pg*8)
    const int x0 = blockIdx.x * PX;
    const int yy = blockIdx.y;
    const int b  = blockIdx.z;

    // Phase 0: taps (px innermost -> coalesced offset reads)
    for (int j = t; j < 9 * PX; j += 128) {
        int px = j & (PX - 1);
        int k  = j >> 6;
        int gx = x0 + px;
        float dy = off[((b * 18 + 2 * k) * HH + yy) * WW + gx];
        float dx = off[((b * 18 + 2 * k + 1) * HH + yy) * WW + gx];
        int ky = k / 3;
        int kx = k - ky * 3;
        float py  = (float)(yy + ky - 1) + dy;
        float pxx = (float)(gx + kx - 1) + dx;
        float fy = floorf(py), fx = floorf(pxx);
        t_y0[j] = (int)fy;
        t_x0[j] = (int)fx;
        t_wy[j] = py - fy;
        t_wx[j] = pxx - fx;
    }

    float acc[OT][8];
    #pragma unroll
    for (int i = 0; i < OT; i++)
        #pragma unroll
        for (int p = 0; p < 8; p++) acc[i][p] = 0.f;

    const float* xb = x + b * C * HH * WW;

    for (int c0 = 0; c0 < C; c0 += CC) {
        __syncthreads();  // taps ready (1st iter) / prior phase B done
        // weight slab: rows [c0*9, c0*9 + CC*9) of wt, fully contiguous
        for (int i = t; i < CC * 9 * O / 4; i += 128)
            ((float4*)w_s)[i] = ((const float4*)(wt + c0 * 9 * O))[i];
        // phase A: bilinear samples (px innermost -> coalesced gathers)
        for (int j = t; j < CC * 9 * PX; j += 128) {
            int px = j & (PX - 1);
            int kj = j >> 6;             // cc*9 + k
            int cc = kj / 9;
            int k  = kj - cc * 9;
            int ti = k * PX + px;
            int yi = t_y0[ti], xi = t_x0[ti];
            float wyv = t_wy[ti], wxv = t_wx[ti];
            const float* xc = xb + (c0 + cc) * HH * WW;
            float a00 = 0.f, a01 = 0.f, a10 = 0.f, a11 = 0.f;
            bool xin0 = (unsigned)xi < (unsigned)WW;
            bool xin1 = (unsigned)(xi + 1) < (unsigned)WW;
            if ((unsigned)yi < (unsigned)HH) {
                const float* row = xc + yi * WW;
                if (xin0) a00 = row[xi];
                if (xin1) a01 = row[xi + 1];
            }
            if ((unsigned)(yi + 1) < (unsigned)HH) {
                const float* row = xc + (yi + 1) * WW;
                if (xin0) a10 = row[xi];
                if (xin1) a11 = row[xi + 1];
            }
            float v0 = a00 + (a01 - a00) * wxv;
            float v1 = a10 + (a11 - a10) * wxv;
            val_s[j] = v0 + (v1 - v0) * wyv;
        }
        __syncthreads();
        // phase B: outer-product accumulate, 8 px x OT oc per thread
        #pragma unroll 4
        for (int kk = 0; kk < CC * 9; kk++) {
            float4 va = *(const float4*)&val_s[kk * PX + pg * 8];
            float4 vb = *(const float4*)&val_s[kk * PX + pg * 8 + 4];
            const float* wrow = &w_s[kk * O + og * OT];
            #pragma unroll
            for (int i4 = 0; i4 < OT; i4 += 4) {
                float4 w4 = *(const float4*)&wrow[i4];
                #pragma unroll
                for (int u = 0; u < 4; u++) {
                    float wv = (u == 0) ? w4.x : (u == 1) ? w4.y : (u == 2) ? w4.z : w4.w;
                    acc[i4 + u][0] += wv * va.x;
                    acc[i4 + u][1] += wv * va.y;
                    acc[i4 + u][2] += wv * va.z;
                    acc[i4 + u][3] += wv * va.w;
                    acc[i4 + u][4] += wv * vb.x;
                    acc[i4 + u][5] += wv * vb.y;
                    acc[i4 + u][6] += wv * vb.z;
                    acc[i4 + u][7] += wv * vb.w;
                }
            }
        }
    }

    const int gx = x0 + pg * 8;
    #pragma unroll
    for (int i = 0; i < OT; i++) {
        int o = og * OT + i;
        float bvv = bias[o];
        float4 r0, r1;
        r0.x = lrelu(acc[i][0] + bvv);
        r0.y = lrelu(acc[i][1] + bvv);
        r0.z = lrelu(acc[i][2] + bvv);
        r0.w = lrelu(acc[i][3] + bvv);
        r1.x = lrelu(acc[i][4] + bvv);
        r1.y = lrelu(acc[i][5] + bvv);
        r1.z = lrelu(acc[i][6] + bvv);
        r1.w = lrelu(acc[i][7] + bvv);
        float* yo = &y[((b * O + o) * HH + yy) * WW + gx];
        *(float4*)yo       = r0;
        *(float4*)(yo + 4) = r1;
    }
}

// ---------------------------------------------------------------------------
// Launch: 3 stages of conv(+leaky) -> offset conv -> deform conv(+leaky),
// each preceded by its weight transposes. Default stream, graph-capturable.
// ---------------------------------------------------------------------------
extern "C" void kernel_launch(void* const* d_in, const int* in_sizes, int n_in,
                              void* d_out, int out_size)
{
    const float* x = (const float*)d_in[0];
    const float* p[18];
    for (int i = 0; i < 18; i++) p[i] = (const float*)d_in[1 + i];

    float *A, *Bf, *OFF, *WTC, *WTO, *WTD;
    cudaGetSymbolAddress((void**)&A,   g_A);
    cudaGetSymbolAddress((void**)&Bf,  g_B);
    cudaGetSymbolAddress((void**)&OFF, g_off);
    cudaGetSymbolAddress((void**)&WTC, g_wtc);
    cudaGetSymbolAddress((void**)&WTO, g_wto);
    cudaGetSymbolAddress((void**)&WTD, g_wtd);

    const int smemD128 = (2304 + 4 * 9 * 64 + 4 * 9 * 128) * 4;  // 36864
    const int smemD64  = (2304 + 4 * 9 * 64 + 4 * 9 * 64) * 4;   // 27648
    cudaFuncSetAttribute(dconv3x3_kernel<128, 128>,
                         cudaFuncAttributeMaxDynamicSharedMemorySize, smemD128);
    cudaFuncSetAttribute(dconv3x3_kernel<64, 64>,
                         cudaFuncAttributeMaxDynamicSharedMemorySize, smemD64);

    dim3 blk(128);
    dim3 dgrid(WW / 64, HH, BB);

    #define WTP(src, dst, C9, O, OP) \
        wt_pad_kernel<<<((C9) * (OP) + 255) / 256, 256>>>(src, dst, C9, O, OP)

    // ---- stage 1: 64 -> 128 ----
    WTP(p[0], WTC, 64 * 9, 128, 128);
    WTP(p[2], WTO, 128 * 9, 18, 24);
    WTP(p[4], WTD, 128 * 9, 128, 128);
    conv3x3_kernel<64, 16, true><<<dim3(4, 8, BB * 8), blk>>>(x, WTC, p[1], A, 128, 128, 8);
    conv3x3_kernel<128, 8, false><<<dim3(4, 8, BB * 3), blk>>>(A, WTO, p[3], OFF, 18, 24, 3);
    dconv3x3_kernel<128, 128><<<dgrid, blk, smemD128>>>(A, OFF, WTD, p[5], Bf);

    // ---- stage 2: 128 -> 128 ----
    WTP(p[6], WTC, 128 * 9, 128, 128);
    WTP(p[8], WTO, 128 * 9, 18, 24);
    WTP(p[10], WTD, 128 * 9, 128, 128);
    conv3x3_kernel<128, 16, true><<<dim3(4, 8, BB * 8), blk>>>(Bf, WTC, p[7], A, 128, 128, 8);
    conv3x3_kernel<128, 8, false><<<dim3(4, 8, BB * 3), blk>>>(A, WTO, p[9], OFF, 18, 24, 3);
    dconv3x3_kernel<128, 128><<<dgrid, blk, smemD128>>>(A, OFF, WTD, p[11], Bf);

    // ---- stage 3: 128 -> 64 ----
    WTP(p[12], WTC, 128 * 9, 64, 64);
    WTP(p[14], WTO, 64 * 9, 18, 24);
    WTP(p[16], WTD, 64 * 9, 64, 64);
    conv3x3_kernel<128, 16, true><<<dim3(4, 8, BB * 4), blk>>>(Bf, WTC, p[13], A, 64, 64, 4);
    conv3x3_kernel<64, 8, false><<<dim3(4, 8, BB * 3), blk>>>(A, WTO, p[15], OFF, 18, 24, 3);
    dconv3x3_kernel<64, 64><<<dgrid, blk, smemD64>>>(A, OFF, WTD, p[17], (float*)d_out);

    #undef WTP
}

// round 4
// speedup vs baseline: 1.1857x; 1.1857x over previous
#include <cuda_runtime.h>
#include <math.h>

// Problem constants (fixed by reference: x = (4, 64, 128, 128) fp32)
#define HH 128
#define WW 128
#define BB 4

// Scratch (allocation-free: __device__ globals)
__device__ float g_A[BB * 128 * HH * WW];   // 32 MB ping
__device__ float g_B[BB * 128 * HH * WW];   // 32 MB pong
__device__ float g_off[BB * 18 * HH * WW];  // offsets
__device__ float g_wtc[128 * 9 * 128];      // transposed conv weights  [cin*9][OP]
__device__ float g_wto[128 * 9 * 24];       // transposed offset-conv weights (pad 24)
__device__ float g_wtd[128 * 9 * 128];      // transposed deform weights [c*9+k][O]

typedef unsigned long long u64;

// Packed fp32x2 ops (Blackwell FFMA2 — only reachable via PTX)
#define FMA2(d, a, b, c) \
    asm("fma.rn.f32x2 %0, %1, %2, %3;" : "=l"(d) : "l"(a), "l"(b), "l"(c))
#define PACKDUP(out, f) \
    asm("mov.b64 %0, {%1, %1};" : "=l"(out) : "r"(__float_as_uint(f)))
#define UNPACK2(lo, hi, in) \
    asm("mov.b64 {%0, %1}, %2;" : "=r"(lo), "=r"(hi) : "l"(in))

__device__ __forceinline__ float lrelu(float v) { return v >= 0.f ? v : 0.2f * v; }

// ---------------------------------------------------------------------------
// Weight transpose + pad: wt[j*OP + o] = (o < O) ? w[o*C9 + j] : 0
// ---------------------------------------------------------------------------
__global__ void wt_pad_kernel(const float* __restrict__ w, float* __restrict__ wt,
                              int C9, int O, int OP)
{
    int idx = blockIdx.x * 256 + threadIdx.x;
    if (idx < C9 * OP) {
        int j = idx / OP;
        int o = idx - j * OP;
        wt[idx] = (o < O) ? w[o * C9 + j] : 0.f;
    }
}

// ---------------------------------------------------------------------------
// Plain 3x3 conv, stride 1, pad 1, optional LeakyReLU.
// Tile: 32(x) x 16(y) px, OCB oc per block, 128 threads.
// Thread: 4 px x OCB oc, accumulated as OCB/2 f32x2 channel-pairs.
// Weights pre-transposed [cin*9][OP] -> pair loads are 64-bit smem reads.
// ---------------------------------------------------------------------------
template<int CIN, int OCB, bool RELU>
__global__ __launch_bounds__(128)
void conv3x3_kernel(const float* __restrict__ x, const float* __restrict__ wt,
                    const float* __restrict__ bias, float* __restrict__ y,
                    int Cout, int OP, int n_ocb)
{
    __shared__ float w_s[36][OCB];     // rows 8B-aligned (OCB multiple of 8)
    __shared__ float in_s[4][18][34];

    const int t   = threadIdx.x;
    const int lx  = t & 7;
    const int ly  = t >> 3;
    const int bx  = blockIdx.x * 32;
    const int by  = blockIdx.y * 16;
    const int b   = blockIdx.z / n_ocb;
    const int ocb = blockIdx.z % n_ocb;
    const int oc0 = ocb * OCB;

    u64 acc[OCB / 2][4];
    #pragma unroll
    for (int q = 0; q < OCB / 2; q++)
        #pragma unroll
        for (int p = 0; p < 4; p++) acc[q][p] = 0ull;

    const float* xb = x + b * CIN * HH * WW;

    for (int c0 = 0; c0 < CIN; c0 += 4) {
        __syncthreads();
        // Stage weights: rows [c0*9, c0*9+36), cols [oc0, oc0+OCB)
        for (int i = t; i < 36 * OCB; i += 128) {
            int row = i / OCB;
            int col = i - row * OCB;
            w_s[row][col] = wt[(c0 * 9 + row) * OP + oc0 + col];
        }
        // Load 4 input channels of a (16+2) x (32+2) halo tile
        for (int i = t; i < 4 * 18 * 34; i += 128) {
            int cc  = i / (18 * 34);
            int rem = i - cc * (18 * 34);
            int r   = rem / 34;
            int col = rem - r * 34;
            int gy  = by - 1 + r;
            int gx  = bx - 1 + col;
            float v = 0.f;
            if ((unsigned)gy < (unsigned)HH && (unsigned)gx < (unsigned)WW)
                v = xb[(c0 + cc) * HH * WW + gy * WW + gx];
            in_s[cc][r][col] = v;
        }
        __syncthreads();
        #pragma unroll
        for (int cc = 0; cc < 4; cc++) {
            float in[3][6];
            #pragma unroll
            for (int r = 0; r < 3; r++)
                #pragma unroll
                for (int cl = 0; cl < 6; cl++)
                    in[r][cl] = in_s[cc][ly + r][lx * 4 + cl];
            #pragma unroll
            for (int j = 0; j < 9; j++) {
                int ry = j / 3, rx = j - ry * 3;
                u64 iv2[4];
                #pragma unroll
                for (int p = 0; p < 4; p++) PACKDUP(iv2[p], in[ry][p + rx]);
                const u64* wp = (const u64*)&w_s[cc * 9 + j][0];
                #pragma unroll
                for (int q = 0; q < OCB / 2; q++) {
                    u64 w2 = wp[q];
                    #pragma unroll
                    for (int p = 0; p < 4; p++)
                        FMA2(acc[q][p], w2, iv2[p], acc[q][p]);
                }
            }
        }
    }

    const int gy = by + ly;
    const int gx = bx + lx * 4;
    #pragma unroll
    for (int q = 0; q < OCB / 2; q++) {
        float lo[4], hi[4];
        #pragma unroll
        for (int p = 0; p < 4; p++) {
            unsigned int ul, uh;
            UNPACK2(ul, uh, acc[q][p]);
            lo[p] = __uint_as_float(ul);
            hi[p] = __uint_as_float(uh);
        }
        #pragma unroll
        for (int h = 0; h < 2; h++) {
            int oc = 2 * q + h;
            if (oc0 + oc < Cout) {
                float bvv = bias[oc0 + oc];
                const float* s = h ? hi : lo;
                float v0 = s[0] + bvv, v1 = s[1] + bvv;
                float v2 = s[2] + bvv, v3 = s[3] + bvv;
                if (RELU) { v0 = lrelu(v0); v1 = lrelu(v1); v2 = lrelu(v2); v3 = lrelu(v3); }
                *(float4*)&y[((b * Cout + oc0 + oc) * HH + gy) * WW + gx] =
                    make_float4(v0, v1, v2, v3);
            }
        }
    }
}

// ---------------------------------------------------------------------------
// Deformable 3x3 conv + LeakyReLU (torchvision semantics, no modulation).
// Block: 256 threads, 64 consecutive x pixels on one row, all O channels.
// CC=8 chunks. Thread = (og 0..15, pg 0..15): OT oc x 4 px, accumulated
// as OT/2 f32x2 channel-pairs. Phase B per k-step: 1 LDS.128 (val),
// OT/2 64-bit w loads, 4 packs, 2*OT FMA2.
// ---------------------------------------------------------------------------
template<int C, int O>
__global__ __launch_bounds__(256)
void dconv3x3_kernel(const float* __restrict__ x, const float* __restrict__ off,
                     const float* __restrict__ wt, const float* __restrict__ bias,
                     float* __restrict__ y)
{
    constexpr int CC = 8;
    constexpr int PX = 64;
    constexpr int OT = O / 16;          // 8 (O=128) or 4 (O=64)
    extern __shared__ float dsm[];
    float* t_wy  = dsm;                      // 576
    float* t_wx  = dsm + 576;                // 576
    int*   t_y0  = (int*)(dsm + 1152);       // 576
    int*   t_x0  = (int*)(dsm + 1728);       // 576
    float* val_s = dsm + 2304;               // CC*9*PX = 4608
    float* w_s   = dsm + 2304 + CC * 9 * PX; // CC*9*O

    const int t  = threadIdx.x;
    const int og = t >> 4;               // 0..15
    const int pg = t & 15;               // 0..15 (px base = pg*4)
    const int x0 = blockIdx.x * PX;
    const int yy = blockIdx.y;
    const int b  = blockIdx.z;

    // Phase 0: taps (px innermost -> coalesced offset reads)
    for (int j = t; j < 9 * PX; j += 256) {
        int px = j & (PX - 1);
        int k  = j >> 6;
        int gx = x0 + px;
        float dy = off[((b * 18 + 2 * k) * HH + yy) * WW + gx];
        float dx = off[((b * 18 + 2 * k + 1) * HH + yy) * WW + gx];
        int ky = k / 3;
        int kx = k - ky * 3;
        float py  = (float)(yy + ky - 1) + dy;
        float pxx = (float)(gx + kx - 1) + dx;
        float fy = floorf(py), fx = floorf(pxx);
        t_y0[j] = (int)fy;
        t_x0[j] = (int)fx;
        t_wy[j] = py - fy;
        t_wx[j] = pxx - fx;
    }

    u64 acc[OT / 2][4];
    #pragma unroll
    for (int q = 0; q < OT / 2; q++)
        #pragma unroll
        for (int p = 0; p < 4; p++) acc[q][p] = 0ull;

    const float* xb = x + b * C * HH * WW;

    for (int c0 = 0; c0 < C; c0 += CC) {
        __syncthreads();  // taps ready (1st iter) / prior phase B done
        // weight slab: rows [c0*9, c0*9 + CC*9) of wt, fully contiguous
        for (int i = t; i < CC * 9 * O / 4; i += 256)
            ((float4*)w_s)[i] = ((const float4*)(wt + c0 * 9 * O))[i];
        // phase A: bilinear samples (px innermost -> coalesced gathers)
        for (int j = t; j < CC * 9 * PX; j += 256) {
            int px = j & (PX - 1);
            int kj = j >> 6;             // cc*9 + k
            int cc = kj / 9;
            int k  = kj - cc * 9;
            int ti = k * PX + px;
            int yi = t_y0[ti], xi = t_x0[ti];
            float wyv = t_wy[ti], wxv = t_wx[ti];
            const float* xc = xb + (c0 + cc) * HH * WW;
            float a00 = 0.f, a01 = 0.f, a10 = 0.f, a11 = 0.f;
            bool xin0 = (unsigned)xi < (unsigned)WW;
            bool xin1 = (unsigned)(xi + 1) < (unsigned)WW;
            if ((unsigned)yi < (unsigned)HH) {
                const float* row = xc + yi * WW;
                if (xin0) a00 = row[xi];
                if (xin1) a01 = row[xi + 1];
            }
            if ((unsigned)(yi + 1) < (unsigned)HH) {
                const float* row = xc + (yi + 1) * WW;
                if (xin0) a10 = row[xi];
                if (xin1) a11 = row[xi + 1];
            }
            float v0 = a00 + (a01 - a00) * wxv;
            float v1 = a10 + (a11 - a10) * wxv;
            val_s[j] = v0 + (v1 - v0) * wyv;
        }
        __syncthreads();
        // phase B: packed outer-product accumulate
        #pragma unroll 4
        for (int kk = 0; kk < CC * 9; kk++) {
            float4 v4 = *(const float4*)&val_s[kk * PX + pg * 4];
            u64 vv[4];
            PACKDUP(vv[0], v4.x);
            PACKDUP(vv[1], v4.y);
            PACKDUP(vv[2], v4.z);
            PACKDUP(vv[3], v4.w);
            const u64* wp = (const u64*)&w_s[kk * O + og * OT];
            #pragma unroll
            for (int q = 0; q < OT / 2; q++) {
                u64 w2 = wp[q];
                #pragma unroll
                for (int p = 0; p < 4; p++)
                    FMA2(acc[q][p], w2, vv[p], acc[q][p]);
            }
        }
    }

    const int gx = x0 + pg * 4;
    #pragma unroll
    for (int q = 0; q < OT / 2; q++) {
        float lo[4], hi[4];
        #pragma unroll
        for (int p = 0; p < 4; p++) {
            unsigned int ul, uh;
            UNPACK2(ul, uh, acc[q][p]);
            lo[p] = __uint_as_float(ul);
            hi[p] = __uint_as_float(uh);
        }
        #pragma unroll
        for (int h = 0; h < 2; h++) {
            int o = og * OT + 2 * q + h;
            float bvv = bias[o];
            const float* s = h ? hi : lo;
            float4 r4;
            r4.x = lrelu(s[0] + bvv);
            r4.y = lrelu(s[1] + bvv);
            r4.z = lrelu(s[2] + bvv);
            r4.w = lrelu(s[3] + bvv);
            *(float4*)&y[((b * O + o) * HH + yy) * WW + gx] = r4;
        }
    }
}

// ---------------------------------------------------------------------------
// Launch: 3 stages of conv(+leaky) -> offset conv -> deform conv(+leaky),
// each preceded by its weight transposes. Default stream, graph-capturable.
// ---------------------------------------------------------------------------
extern "C" void kernel_launch(void* const* d_in, const int* in_sizes, int n_in,
                              void* d_out, int out_size)
{
    const float* x = (const float*)d_in[0];
    const float* p[18];
    for (int i = 0; i < 18; i++) p[i] = (const float*)d_in[1 + i];

    float *A, *Bf, *OFF, *WTC, *WTO, *WTD;
    cudaGetSymbolAddress((void**)&A,   g_A);
    cudaGetSymbolAddress((void**)&Bf,  g_B);
    cudaGetSymbolAddress((void**)&OFF, g_off);
    cudaGetSymbolAddress((void**)&WTC, g_wtc);
    cudaGetSymbolAddress((void**)&WTO, g_wto);
    cudaGetSymbolAddress((void**)&WTD, g_wtd);

    const int smemD128 = (2304 + 8 * 9 * 64 + 8 * 9 * 128) * 4;  // 64512
    const int smemD64  = (2304 + 8 * 9 * 64 + 8 * 9 * 64) * 4;   // 46080
    cudaFuncSetAttribute(dconv3x3_kernel<128, 128>,
                         cudaFuncAttributeMaxDynamicSharedMemorySize, smemD128);
    cudaFuncSetAttribute(dconv3x3_kernel<64, 64>,
                         cudaFuncAttributeMaxDynamicSharedMemorySize, smemD64);

    dim3 blk128(128), blk256(256);
    dim3 dgrid(WW / 64, HH, BB);

    #define WTP(src, dst, C9, O, OP) \
        wt_pad_kernel<<<((C9) * (OP) + 255) / 256, 256>>>(src, dst, C9, O, OP)

    // ---- stage 1: 64 -> 128 ----
    WTP(p[0], WTC, 64 * 9, 128, 128);
    WTP(p[2], WTO, 128 * 9, 18, 24);
    WTP(p[4], WTD, 128 * 9, 128, 128);
    conv3x3_kernel<64, 16, true><<<dim3(4, 8, BB * 8), blk128>>>(x, WTC, p[1], A, 128, 128, 8);
    conv3x3_kernel<128, 8, false><<<dim3(4, 8, BB * 3), blk128>>>(A, WTO, p[3], OFF, 18, 24, 3);
    dconv3x3_kernel<128, 128><<<dgrid, blk256, smemD128>>>(A, OFF, WTD, p[5], Bf);

    // ---- stage 2: 128 -> 128 ----
    WTP(p[6], WTC, 128 * 9, 128, 128);
    WTP(p[8], WTO, 128 * 9, 18, 24);
    WTP(p[10], WTD, 128 * 9, 128, 128);
    conv3x3_kernel<128, 16, true><<<dim3(4, 8, BB * 8), blk128>>>(Bf, WTC, p[7], A, 128, 128, 8);
    conv3x3_kernel<128, 8, false><<<dim3(4, 8, BB * 3), blk128>>>(A, WTO, p[9], OFF, 18, 24, 3);
    dconv3x3_kernel<128, 128><<<dgrid, blk256, smemD128>>>(A, OFF, WTD, p[11], Bf);

    // ---- stage 3: 128 -> 64 ----
    WTP(p[12], WTC, 128 * 9, 64, 64);
    WTP(p[14], WTO, 64 * 9, 18, 24);
    WTP(p[16], WTD, 64 * 9, 64, 64);
    conv3x3_kernel<128, 16, true><<<dim3(4, 8, BB * 4), blk128>>>(Bf, WTC, p[13], A, 64, 64, 4);
    conv3x3_kernel<64, 8, false><<<dim3(4, 8, BB * 3), blk128>>>(A, WTO, p[15], OFF, 18, 24, 3);
    dconv3x3_kernel<64, 64><<<dgrid, blk256, smemD64>>>(A, OFF, WTD, p[17], (float*)d_out);

    #undef WTP
}

// round 5
// speedup vs baseline: 1.3669x; 1.1528x over previous
#include <cuda_runtime.h>
#include <math.h>

// Problem constants (fixed by reference: x = (4, 64, 128, 128) fp32)
#define HH 128
#define WW 128
#define BB 4

// Scratch (allocation-free: __device__ globals)
__device__ float g_A[BB * 128 * HH * WW];   // 32 MB ping
__device__ float g_B[BB * 128 * HH * WW];   // 32 MB pong
__device__ float g_off[BB * 18 * HH * WW];  // offsets
__device__ float g_wtc[128 * 9 * 128];      // transposed conv weights  [cin*9][OP]
__device__ float g_wto[128 * 9 * 24];       // transposed offset-conv weights (pad 24)
__device__ float g_wtd[128 * 9 * 128];      // transposed deform weights [c*9+k][O]

typedef unsigned long long u64;

// Packed fp32x2 ops (Blackwell FFMA2 — only reachable via PTX)
#define FMA2(d, a, b, c) \
    asm("fma.rn.f32x2 %0, %1, %2, %3;" : "=l"(d) : "l"(a), "l"(b), "l"(c))
#define PACKDUP(out, f) \
    asm("mov.b64 %0, {%1, %1};" : "=l"(out) : "r"(__float_as_uint(f)))
#define UNPACK2(lo, hi, in) \
    asm("mov.b64 {%0, %1}, %2;" : "=r"(lo), "=r"(hi) : "l"(in))

// cp.async (LDGSTS)
#define CP_ASYNC4(dst_s, src_g, szr) \
    asm volatile("cp.async.ca.shared.global [%0], [%1], 4, %2;" \
                 :: "r"(dst_s), "l"(src_g), "r"(szr))
#define CP_ASYNC16(dst_s, src_g) \
    asm volatile("cp.async.ca.shared.global [%0], [%1], 16;" \
                 :: "r"(dst_s), "l"(src_g))
#define CP_COMMIT() asm volatile("cp.async.commit_group;")
#define CP_WAIT0()  asm volatile("cp.async.wait_group 0;")

__device__ __forceinline__ unsigned s2u(const void* p) {
    return (unsigned)__cvta_generic_to_shared(p);
}
__device__ __forceinline__ float lrelu(float v) { return v >= 0.f ? v : 0.2f * v; }

// ---------------------------------------------------------------------------
// Weight transpose + pad: wt[j*OP + o] = (o < O) ? w[o*C9 + j] : 0
// ---------------------------------------------------------------------------
__global__ void wt_pad_kernel(const float* __restrict__ w, float* __restrict__ wt,
                              int C9, int O, int OP)
{
    int idx = blockIdx.x * 256 + threadIdx.x;
    if (idx < C9 * OP) {
        int j = idx / OP;
        int o = idx - j * OP;
        wt[idx] = (o < O) ? w[o * C9 + j] : 0.f;
    }
}

// ---------------------------------------------------------------------------
// Plain 3x3 conv, stride 1, pad 1, optional LeakyReLU.
// 32(x) x 16(y) px tile, OCB oc per block, 128 threads.
// Thread: 4 px x OCB oc as OCB/2 f32x2 pairs.
// cp.async double-buffered input halo + weight slab, 1 barrier per chunk.
// ---------------------------------------------------------------------------
template<int CIN, int OCB, bool RELU>
__global__ __launch_bounds__(128)
void conv3x3_kernel(const float* __restrict__ x, const float* __restrict__ wt,
                    const float* __restrict__ bias, float* __restrict__ y,
                    int Cout, int OP, int n_ocb)
{
    __shared__ float w_s[2][36][OCB];
    __shared__ float in_s[2][4][18][34];

    const int t   = threadIdx.x;
    const int lx  = t & 7;
    const int ly  = t >> 3;
    const int bx  = blockIdx.x * 32;
    const int by  = blockIdx.y * 16;
    const int b   = blockIdx.z / n_ocb;
    const int ocb = blockIdx.z % n_ocb;
    const int oc0 = ocb * OCB;

    const float* xb = x + b * CIN * HH * WW;

    u64 acc[OCB / 2][4];
    #pragma unroll
    for (int q = 0; q < OCB / 2; q++)
        #pragma unroll
        for (int p = 0; p < 4; p++) acc[q][p] = 0ull;

    // async chunk loader: 4 input channels + weight slab into buffer bi
    auto load_chunk = [&](int c0, int bi) {
        const float* xc = xb + c0 * HH * WW;
        unsigned in_base = s2u(&in_s[bi][0][0][0]);
        for (int i = t; i < 4 * 18 * 34; i += 128) {
            int cc  = i / (18 * 34);
            int rem = i - cc * (18 * 34);
            int r   = rem / 34;
            int col = rem - r * 34;
            int gy  = by - 1 + r;
            int gx  = bx - 1 + col;
            bool ok = ((unsigned)gy < (unsigned)HH) & ((unsigned)gx < (unsigned)WW);
            const float* src = xc + cc * HH * WW + (ok ? gy * WW + gx : 0);
            int sz = ok ? 4 : 0;
            CP_ASYNC4(in_base + i * 4, src, sz);
        }
        for (int i = t; i < 36 * (OCB / 4); i += 128) {
            int row = i / (OCB / 4);
            int q   = i - row * (OCB / 4);
            CP_ASYNC16(s2u(&w_s[bi][row][q * 4]),
                       &wt[(c0 * 9 + row) * OP + oc0 + q * 4]);
        }
    };

    load_chunk(0, 0);
    CP_COMMIT();

    int buf = 0;
    for (int c0 = 0; c0 < CIN; c0 += 4) {
        CP_WAIT0();
        __syncthreads();
        if (c0 + 4 < CIN) { load_chunk(c0 + 4, buf ^ 1); CP_COMMIT(); }

        #pragma unroll
        for (int cc = 0; cc < 4; cc++) {
            #pragma unroll
            for (int ry = 0; ry < 3; ry++) {
                float rowv[6];
                #pragma unroll
                for (int cl = 0; cl < 6; cl++)
                    rowv[cl] = in_s[buf][cc][ly + ry][lx * 4 + cl];
                #pragma unroll
                for (int rx = 0; rx < 3; rx++) {
                    u64 iv2[4];
                    #pragma unroll
                    for (int p = 0; p < 4; p++) PACKDUP(iv2[p], rowv[p + rx]);
                    const u64* wp = (const u64*)&w_s[buf][cc * 9 + ry * 3 + rx][0];
                    #pragma unroll
                    for (int q = 0; q < OCB / 2; q++) {
                        u64 w2 = wp[q];
                        #pragma unroll
                        for (int p = 0; p < 4; p++)
                            FMA2(acc[q][p], w2, iv2[p], acc[q][p]);
                    }
                }
            }
        }
        buf ^= 1;
    }

    const int gy = by + ly;
    const int gx = bx + lx * 4;
    #pragma unroll
    for (int q = 0; q < OCB / 2; q++) {
        float lo[4], hi[4];
        #pragma unroll
        for (int p = 0; p < 4; p++) {
            unsigned int ul, uh;
            UNPACK2(ul, uh, acc[q][p]);
            lo[p] = __uint_as_float(ul);
            hi[p] = __uint_as_float(uh);
        }
        #pragma unroll
        for (int h = 0; h < 2; h++) {
            int oc = 2 * q + h;
            if (oc0 + oc < Cout) {
                float bvv = bias[oc0 + oc];
                const float* s = h ? hi : lo;
                float v0 = s[0] + bvv, v1 = s[1] + bvv;
                float v2 = s[2] + bvv, v3 = s[3] + bvv;
                if (RELU) { v0 = lrelu(v0); v1 = lrelu(v1); v2 = lrelu(v2); v3 = lrelu(v3); }
                *(float4*)&y[((b * Cout + oc0 + oc) * HH + gy) * WW + gx] =
                    make_float4(v0, v1, v2, v3);
            }
        }
    }
}

// ---------------------------------------------------------------------------
// Deformable 3x3 conv + LeakyReLU.
// 256 threads, 64 px on one row, all O channels. CC=4 chunks,
// double-buffered val + weights (cp.async), one barrier per chunk.
// Per iteration: phase B(i) [FMA2 stream] then phase A(i+1) [gathers] —
// cross-warp overlap hides gather latency behind math.
// ---------------------------------------------------------------------------
template<int C, int O>
__global__ __launch_bounds__(256)
void dconv3x3_kernel(const float* __restrict__ x, const float* __restrict__ off,
                     const float* __restrict__ wt, const float* __restrict__ bias,
                     float* __restrict__ y)
{
    constexpr int CC = 4;
    constexpr int PX = 64;
    constexpr int KS = CC * 9;          // 36
    constexpr int NC = C / CC;
    constexpr int OT = O / 16;          // 8 (O=128) or 4 (O=64)
    extern __shared__ float dsm[];
    float* t_wy  = dsm;                       // 576
    float* t_wx  = dsm + 576;                 // 576
    int*   t_y0  = (int*)(dsm + 1152);        // 576
    int*   t_x0  = (int*)(dsm + 1728);        // 576
    float* val_s = dsm + 2304;                // 2 * KS * PX
    float* w_s   = dsm + 2304 + 2 * KS * PX;  // 2 * KS * O

    const int t  = threadIdx.x;
    const int og = t >> 4;               // 0..15
    const int pg = t & 15;               // 0..15 (px base = pg*4)
    const int x0 = blockIdx.x * PX;
    const int yy = blockIdx.y;
    const int b  = blockIdx.z;

    // Phase 0: taps (px innermost -> coalesced offset reads)
    for (int j = t; j < 9 * PX; j += 256) {
        int px = j & (PX - 1);
        int k  = j >> 6;
        int gx = x0 + px;
        float dy = off[((b * 18 + 2 * k) * HH + yy) * WW + gx];
        float dx = off[((b * 18 + 2 * k + 1) * HH + yy) * WW + gx];
        int ky = k / 3;
        int kx = k - ky * 3;
        float py  = (float)(yy + ky - 1) + dy;
        float pxx = (float)(gx + kx - 1) + dx;
        float fy = floorf(py), fx = floorf(pxx);
        t_y0[j] = (int)fy;
        t_x0[j] = (int)fx;
        t_wy[j] = py - fy;
        t_wx[j] = pxx - fx;
    }

    const float* xb = x + b * C * HH * WW;

    auto load_w = [&](int ci, int bi) {
        const float4* src = (const float4*)(wt + ci * KS * O);
        float* dst = w_s + bi * KS * O;
        for (int i = t; i < KS * O / 4; i += 256)
            CP_ASYNC16(s2u(dst + i * 4), src + i);
    };

    auto phaseA = [&](int ci, int bi) {
        float* dst = val_s + bi * KS * PX;
        #pragma unroll 3
        for (int j = t; j < KS * PX; j += 256) {
            int px = j & (PX - 1);
            int kj = j >> 6;             // cc*9 + k
            int cc = kj / 9;
            int k  = kj - cc * 9;
            int ti = k * PX + px;
            int yi = t_y0[ti], xi = t_x0[ti];
            float wyv = t_wy[ti], wxv = t_wx[ti];
            const float* xc = xb + (ci * CC + cc) * HH * WW;
            float a00 = 0.f, a01 = 0.f, a10 = 0.f, a11 = 0.f;
            bool xin0 = (unsigned)xi < (unsigned)WW;
            bool xin1 = (unsigned)(xi + 1) < (unsigned)WW;
            if ((unsigned)yi < (unsigned)HH) {
                const float* row = xc + yi * WW;
                if (xin0) a00 = row[xi];
                if (xin1) a01 = row[xi + 1];
            }
            if ((unsigned)(yi + 1) < (unsigned)HH) {
                const float* row = xc + (yi + 1) * WW;
                if (xin0) a10 = row[xi];
                if (xin1) a11 = row[xi + 1];
            }
            float v0 = a00 + (a01 - a00) * wxv;
            float v1 = a10 + (a11 - a10) * wxv;
            dst[j] = v0 + (v1 - v0) * wyv;
        }
    };

    u64 acc[OT / 2][4];
    #pragma unroll
    for (int q = 0; q < OT / 2; q++)
        #pragma unroll
        for (int p = 0; p < 4; p++) acc[q][p] = 0ull;

    // prologue
    __syncthreads();          // taps visible
    load_w(0, 0);
    CP_COMMIT();
    phaseA(0, 0);

    for (int i = 0; i < NC; i++) {
        CP_WAIT0();
        __syncthreads();      // val(i), w(i) visible; prior buffers free
        if (i + 1 < NC) { load_w(i + 1, (i + 1) & 1); CP_COMMIT(); }

        // phase B(i)
        const float* vb = val_s + (i & 1) * KS * PX;
        const float* wb = w_s + (i & 1) * KS * O;
        #pragma unroll 4
        for (int kk = 0; kk < KS; kk++) {
            float4 v4 = *(const float4*)&vb[kk * PX + pg * 4];
            u64 vv[4];
            PACKDUP(vv[0], v4.x);
            PACKDUP(vv[1], v4.y);
            PACKDUP(vv[2], v4.z);
            PACKDUP(vv[3], v4.w);
            const u64* wp = (const u64*)&wb[kk * O + og * OT];
            #pragma unroll
            for (int q = 0; q < OT / 2; q++) {
                u64 w2 = wp[q];
                #pragma unroll
                for (int p = 0; p < 4; p++)
                    FMA2(acc[q][p], w2, vv[p], acc[q][p]);
            }
        }

        // phase A(i+1)
        if (i + 1 < NC) phaseA(i + 1, (i + 1) & 1);
    }

    const int gx = x0 + pg * 4;
    #pragma unroll
    for (int q = 0; q < OT / 2; q++) {
        float lo[4], hi[4];
        #pragma unroll
        for (int p = 0; p < 4; p++) {
            unsigned int ul, uh;
            UNPACK2(ul, uh, acc[q][p]);
            lo[p] = __uint_as_float(ul);
            hi[p] = __uint_as_float(uh);
        }
        #pragma unroll
        for (int h = 0; h < 2; h++) {
            int o = og * OT + 2 * q + h;
            float bvv = bias[o];
            const float* s = h ? hi : lo;
            float4 r4;
            r4.x = lrelu(s[0] + bvv);
            r4.y = lrelu(s[1] + bvv);
            r4.z = lrelu(s[2] + bvv);
            r4.w = lrelu(s[3] + bvv);
            *(float4*)&y[((b * O + o) * HH + yy) * WW + gx] = r4;
        }
    }
}

// ---------------------------------------------------------------------------
// Launch: 3 stages of conv(+leaky) -> offset conv -> deform conv(+leaky),
// each preceded by its weight transposes. Default stream, graph-capturable.
// ---------------------------------------------------------------------------
extern "C" void kernel_launch(void* const* d_in, const int* in_sizes, int n_in,
                              void* d_out, int out_size)
{
    const float* x = (const float*)d_in[0];
    const float* p[18];
    for (int i = 0; i < 18; i++) p[i] = (const float*)d_in[1 + i];

    float *A, *Bf, *OFF, *WTC, *WTO, *WTD;
    cudaGetSymbolAddress((void**)&A,   g_A);
    cudaGetSymbolAddress((void**)&Bf,  g_B);
    cudaGetSymbolAddress((void**)&OFF, g_off);
    cudaGetSymbolAddress((void**)&WTC, g_wtc);
    cudaGetSymbolAddress((void**)&WTO, g_wto);
    cudaGetSymbolAddress((void**)&WTD, g_wtd);

    // dconv smem: taps(2304) + val(2*36*64) + w(2*36*O) floats
    const int smemD128 = (2304 + 2 * 36 * 64 + 2 * 36 * 128) * 4;  // 64512
    const int smemD64  = (2304 + 2 * 36 * 64 + 2 * 36 * 64) * 4;   // 46080
    cudaFuncSetAttribute(dconv3x3_kernel<128, 128>,
                         cudaFuncAttributeMaxDynamicSharedMemorySize, smemD128);
    cudaFuncSetAttribute(dconv3x3_kernel<64, 64>,
                         cudaFuncAttributeMaxDynamicSharedMemorySize, smemD64);

    dim3 blk128(128), blk256(256);
    dim3 dgrid(WW / 64, HH, BB);

    #define WTP(src, dst, C9, O, OP) \
        wt_pad_kernel<<<((C9) * (OP) + 255) / 256, 256>>>(src, dst, C9, O, OP)

    // ---- stage 1: 64 -> 128 ----
    WTP(p[0], WTC, 64 * 9, 128, 128);
    WTP(p[2], WTO, 128 * 9, 18, 24);
    WTP(p[4], WTD, 128 * 9, 128, 128);
    conv3x3_kernel<64, 16, true><<<dim3(4, 8, BB * 8), blk128>>>(x, WTC, p[1], A, 128, 128, 8);
    conv3x3_kernel<128, 8, false><<<dim3(4, 8, BB * 3), blk128>>>(A, WTO, p[3], OFF, 18, 24, 3);
    dconv3x3_kernel<128, 128><<<dgrid, blk256, smemD128>>>(A, OFF, WTD, p[5], Bf);

    // ---- stage 2: 128 -> 128 ----
    WTP(p[6], WTC, 128 * 9, 128, 128);
    WTP(p[8], WTO, 128 * 9, 18, 24);
    WTP(p[10], WTD, 128 * 9, 128, 128);
    conv3x3_kernel<128, 16, true><<<dim3(4, 8, BB * 8), blk128>>>(Bf, WTC, p[7], A, 128, 128, 8);
    conv3x3_kernel<128, 8, false><<<dim3(4, 8, BB * 3), blk128>>>(A, WTO, p[9], OFF, 18, 24, 3);
    dconv3x3_kernel<128, 128><<<dgrid, blk256, smemD128>>>(A, OFF, WTD, p[11], Bf);

    // ---- stage 3: 128 -> 64 ----
    WTP(p[12], WTC, 128 * 9, 64, 64);
    WTP(p[14], WTO, 64 * 9, 18, 24);
    WTP(p[16], WTD, 64 * 9, 64, 64);
    conv3x3_kernel<128, 16, true><<<dim3(4, 8, BB * 4), blk128>>>(Bf, WTC, p[13], A, 64, 64, 4);
    conv3x3_kernel<64, 8, false><<<dim3(4, 8, BB * 3), blk128>>>(A, WTO, p[15], OFF, 18, 24, 3);
    dconv3x3_kernel<64, 64><<<dgrid, blk256, smemD64>>>(A, OFF, WTD, p[17], (float*)d_out);

    #undef WTP
}